// round 10
// baseline (speedup 1.0000x reference)
#include <cuda_runtime.h>
#include <math.h>
#include <stdint.h>

// Problem constants
#define B_   16
#define N_   1024
#define D_   512
#define C_   4096
#define NTOT (B_ * N_)        // 16384
#define DECAY 0.8f
#define ONE_MINUS_DECAY 0.2f
#define EPS_ 1e-5f

// Output layout (floats), concatenated in reference return order
#define OFF_Q    0ull
#define OFF_IND  (OFF_Q + (unsigned long long)NTOT * D_)
#define OFF_DIST (OFF_IND + NTOT)
#define OFF_NE   (OFF_DIST + (unsigned long long)NTOT * C_)
#define OFF_NCS  (OFF_NE + (unsigned long long)C_ * D_)
#define OFF_NEA  (OFF_NCS + C_)

// GEMM tiling
#define BM 128
#define BN 256
#define BKF 64
#define NNT (C_ / BN)         // 16 n-tiles
#define NMT (NTOT / BM)       // 128 m-tiles

// ---------------------------------------------------------------------------
// Device scratch (static; no runtime allocation allowed)
// ---------------------------------------------------------------------------
__device__ float g_bins[C_];
__device__ float g_embed_sum[(size_t)C_ * D_];
__device__ float g_total;
__device__ float g_xt[(size_t)NTOT * D_];   // tf32-rounded x
__device__ float g_et[(size_t)C_ * D_];     // tf32-rounded embed
__device__ float g_pmax[(size_t)NTOT * NNT];  // per-(row, ntile) approx max

// ---------------------------------------------------------------------------
// PTX helpers (base sm_80-level features only)
// ---------------------------------------------------------------------------
__device__ __forceinline__ uint32_t smem_u32(const void* p) {
    uint32_t a;
    asm("{ .reg .u64 t; cvta.to.shared.u64 t, %1; cvt.u32.u64 %0, t; }"
        : "=r"(a) : "l"(p));
    return a;
}
__device__ __forceinline__ void cp_async16(uint32_t dst, const void* src) {
    asm volatile("cp.async.ca.shared.global [%0], [%1], 16;"
                 :: "r"(dst), "l"(src) : "memory");
}
__device__ __forceinline__ void cp_commit() {
    asm volatile("cp.async.commit_group;" ::: "memory");
}
template <int N>
__device__ __forceinline__ void cp_wait() {
    asm volatile("cp.async.wait_group %0;" :: "n"(N) : "memory");
}
__device__ __forceinline__ float tf32_rna(float v) {
    uint32_t o;
    asm("cvt.rna.tf32.f32 %0, %1;" : "=r"(o) : "f"(v));
    return __uint_as_float(o);
}
__device__ __forceinline__ void mma_tf32(float* d, const uint32_t* a,
                                         const uint32_t* b, const float* c) {
    asm volatile(
        "mma.sync.aligned.m16n8k8.row.col.f32.tf32.tf32.f32 "
        "{%0,%1,%2,%3}, {%4,%5,%6,%7}, {%8,%9}, {%10,%11,%12,%13};"
        : "=f"(d[0]), "=f"(d[1]), "=f"(d[2]), "=f"(d[3])
        : "r"(a[0]), "r"(a[1]), "r"(a[2]), "r"(a[3]),
          "r"(b[0]), "r"(b[1]),
          "f"(c[0]), "f"(c[1]), "f"(c[2]), "f"(c[3]));
}
// monotone float <-> uint encoding (for atomicMax on shared)
__device__ __forceinline__ unsigned fenc(float f) {
    unsigned u = __float_as_uint(f);
    return (u & 0x80000000u) ? ~u : (u | 0x80000000u);
}
__device__ __forceinline__ float fdec(unsigned u) {
    unsigned v = (u & 0x80000000u) ? (u & 0x7fffffffu) : ~u;
    return __uint_as_float(v);
}

// ---------------------------------------------------------------------------
// Kernel 0: zero scratch (bins + embed_sum)
// ---------------------------------------------------------------------------
__global__ void zero_scratch_kernel() {
    size_t total = (size_t)C_ * D_ + C_;
    size_t idx = (size_t)blockIdx.x * blockDim.x + threadIdx.x;
    size_t stride = (size_t)gridDim.x * blockDim.x;
    for (size_t i = idx; i < total; i += stride) {
        if (i < (size_t)C_ * D_) g_embed_sum[i] = 0.0f;
        else g_bins[i - (size_t)C_ * D_] = 0.0f;
    }
}

// ---------------------------------------------------------------------------
// Kernel 1: round fp32 -> tf32 (rna) copies
// ---------------------------------------------------------------------------
__global__ __launch_bounds__(256)
void prep_kernel(const float* __restrict__ in, float* __restrict__ out) {
    size_t i = (size_t)blockIdx.x * 256 + threadIdx.x;
    float4 v = reinterpret_cast<const float4*>(in)[i];
    v.x = tf32_rna(v.x);
    v.y = tf32_rna(v.y);
    v.z = tf32_rna(v.z);
    v.w = tf32_rna(v.w);
    reinterpret_cast<float4*>(out)[i] = v;
}

// ---------------------------------------------------------------------------
// Kernel 2: dist GEMM via mma.sync tf32.
// BM=128 BN=256 BK=64, 256 threads, warp grid 2x4, warp tile 64x64.
// 2-stage cp.async pipeline (102KB/stage), 8 kt iterations.
// Fused per-(row, ntile) max -> g_pmax.
// Smem per stage: A [128][68] + B [256][68] floats (stride 68 conflict-free:
// 68 mod 32 = 4, same bank pattern as stride 36).
// ---------------------------------------------------------------------------
#define ROWSTRIDE 68
#define A_WORDS (BM * ROWSTRIDE)             // 8704
#define B_WORDS (BN * ROWSTRIDE)             // 17408
#define STAGE_WORDS (A_WORDS + B_WORDS)      // 26112 words = 104448 B
#define NSTAGE 2
#define SMEM_GEMM_BYTES (NSTAGE * STAGE_WORDS * 4 + 512 + 128)  // 209536

__global__ __launch_bounds__(256, 1)
void dist_mma_kernel(const float* __restrict__ xt,
                     const float* __restrict__ et,
                     float* __restrict__ dist) {
    extern __shared__ float smem[];
    unsigned* smax = reinterpret_cast<unsigned*>(smem + NSTAGE * STAGE_WORDS);
    const uint32_t sbase = smem_u32(smem);
    const int tid = threadIdx.x;
    const int wid = tid >> 5;
    const int lane = tid & 31;
    const int g = lane >> 2;   // 0..7
    const int q = lane & 3;    // 0..3
    const int wm = (wid >> 2) * 64;  // warp m offset (2 warps in m)
    const int wn = (wid & 3) * 64;   // warp n offset (4 warps in n)

    const int ntile = blockIdx.x;
    const int mtile = blockIdx.y;
    const int m0 = mtile * BM;
    const int c0 = ntile * BN;

    if (tid < BM) smax[tid] = 0u;   // enc(-inf) < any enc

    float acc[4][8][4];
#pragma unroll
    for (int mt = 0; mt < 4; mt++)
#pragma unroll
        for (int nt = 0; nt < 8; nt++)
#pragma unroll
            for (int j = 0; j < 4; j++) acc[mt][nt][j] = 0.0f;

    auto load_stage = [&](int kt, int st) {
        const uint32_t abase = sbase + (uint32_t)(st * STAGE_WORDS) * 4;
        const uint32_t bbase = abase + (uint32_t)A_WORDS * 4;
        // A: 128 rows x 16 float4 = 2048 slots, 8 per thread
#pragma unroll
        for (int l = 0; l < 8; l++) {
            int idx = tid + l * 256;
            int row = idx >> 4;
            int kc = (idx & 15) << 2;
            cp_async16(abase + (uint32_t)(row * ROWSTRIDE + kc) * 4,
                       &xt[(size_t)(m0 + row) * D_ + kt * BKF + kc]);
        }
        // B: 256 rows x 16 float4 = 4096 slots, 16 per thread
#pragma unroll
        for (int l = 0; l < 16; l++) {
            int idx = tid + l * 256;
            int row = idx >> 4;
            int kc = (idx & 15) << 2;
            cp_async16(bbase + (uint32_t)(row * ROWSTRIDE + kc) * 4,
                       &et[(size_t)(c0 + row) * D_ + kt * BKF + kc]);
        }
        cp_commit();
    };

    load_stage(0, 0);

    const int NK = D_ / BKF;   // 8
    for (int kt = 0; kt < NK; kt++) {
        const int st = kt & 1;
        if (kt + 1 < NK) {
            load_stage(kt + 1, st ^ 1);
            cp_wait<1>();
        } else {
            cp_wait<0>();
        }
        __syncthreads();

        const uint32_t* Au = reinterpret_cast<const uint32_t*>(smem + st * STAGE_WORDS);
        const uint32_t* Bu = Au + A_WORDS;

#pragma unroll
        for (int ks = 0; ks < 8; ks++) {
            const int k0 = ks * 8;
            uint32_t a[4][4], b[8][2];
#pragma unroll
            for (int mt = 0; mt < 4; mt++) {
                int r = wm + mt * 16 + g;
                a[mt][0] = Au[r * ROWSTRIDE + k0 + q];
                a[mt][1] = Au[(r + 8) * ROWSTRIDE + k0 + q];
                a[mt][2] = Au[r * ROWSTRIDE + k0 + 4 + q];
                a[mt][3] = Au[(r + 8) * ROWSTRIDE + k0 + 4 + q];
            }
#pragma unroll
            for (int nt = 0; nt < 8; nt++) {
                int rn = wn + nt * 8 + g;
                b[nt][0] = Bu[rn * ROWSTRIDE + k0 + q];
                b[nt][1] = Bu[rn * ROWSTRIDE + k0 + 4 + q];
            }
#pragma unroll
            for (int mt = 0; mt < 4; mt++)
#pragma unroll
                for (int nt = 0; nt < 8; nt++)
                    mma_tf32(acc[mt][nt], a[mt], b[nt], acc[mt][nt]);
        }
        // protect stage st before next iteration's load overwrites it
        __syncthreads();
    }

    // Epilogue: write dist + per-row max (shared atomicMax, enc monotone)
#pragma unroll
    for (int mt = 0; mt < 4; mt++) {
        float mA = -INFINITY, mB = -INFINITY;
#pragma unroll
        for (int nt = 0; nt < 8; nt++) {
            int row = m0 + wm + mt * 16 + g;
            int col = c0 + wn + nt * 8 + 2 * q;
            float2 v01 = make_float2(acc[mt][nt][0], acc[mt][nt][1]);
            float2 v23 = make_float2(acc[mt][nt][2], acc[mt][nt][3]);
            *reinterpret_cast<float2*>(&dist[(size_t)row * C_ + col]) = v01;
            *reinterpret_cast<float2*>(&dist[(size_t)(row + 8) * C_ + col]) = v23;
            mA = fmaxf(mA, fmaxf(v01.x, v01.y));
            mB = fmaxf(mB, fmaxf(v23.x, v23.y));
        }
        atomicMax(&smax[wm + mt * 16 + g], fenc(mA));
        atomicMax(&smax[wm + mt * 16 + 8 + g], fenc(mB));
    }
    __syncthreads();
    if (tid < BM)
        g_pmax[(size_t)(m0 + tid) * NNT + ntile] = fdec(smax[tid]);
}

// ---------------------------------------------------------------------------
// Kernel 3: rescue argmax driven by tile maxes + exact recompute of
//           near-max candidates + gather quantize + scatter embed_sum/bins.
// One block per row n, 128 threads.
// ---------------------------------------------------------------------------
#define MARGIN 3e-3f
#define MAXCAND 32

__global__ __launch_bounds__(128)
void rescue_kernel(const float* __restrict__ dist,
                   const float* __restrict__ x,
                   const float* __restrict__ embed,
                   float* __restrict__ quant_out,
                   float* __restrict__ ind_out) {
    const int n = blockIdx.x;
    const int tid = threadIdx.x;
    __shared__ float spm[NNT];
    __shared__ float sred[128];
    __shared__ int scand[MAXCAND];
    __shared__ int scount;
    __shared__ float sM;
    __shared__ float sbest;
    __shared__ int sbidx;

    if (tid < NNT) spm[tid] = g_pmax[(size_t)n * NNT + tid];
    if (tid == 0) { scount = 0; sbest = -INFINITY; sbidx = 0; }
    __syncthreads();
    if (tid == 0) {
        float M = -INFINITY;
#pragma unroll
        for (int t = 0; t < NNT; t++) M = fmaxf(M, spm[t]);
        sM = M;
    }
    __syncthreads();
    const float thresh = sM - MARGIN;

    const float* drow = dist + (size_t)n * C_;
#pragma unroll 1
    for (int t = 0; t < NNT; t++) {
        if (spm[t] >= thresh) {
#pragma unroll
            for (int i = 0; i < 2; i++) {
                int c = t * BN + i * 128 + tid;
                if (drow[c] >= thresh) {
                    int p = atomicAdd(&scount, 1);
                    if (p < MAXCAND) scand[p] = c;
                }
            }
        }
    }
    __syncthreads();
    int ncand = min(scount, MAXCAND);
    if (tid == 0 && ncand > 1) {
        // insertion sort ascending (first-index tie-break like jnp.argmax)
        for (int i = 1; i < ncand; i++) {
            int key = scand[i];
            int j = i - 1;
            while (j >= 0 && scand[j] > key) { scand[j + 1] = scand[j]; j--; }
            scand[j + 1] = key;
        }
    }
    __syncthreads();

    const float4 x4v = reinterpret_cast<const float4*>(x + (size_t)n * D_)[tid];

    for (int ci = 0; ci < ncand; ci++) {
        const int c = scand[ci];
        const float4 e4 = reinterpret_cast<const float4*>(embed + (size_t)c * D_)[tid];
        float p = x4v.x * e4.x + x4v.y * e4.y + x4v.z * e4.z + x4v.w * e4.w;
        sred[tid] = p;
        __syncthreads();
#pragma unroll
        for (int s = 64; s > 0; s >>= 1) {
            if (tid < s) sred[tid] += sred[tid + s];
            __syncthreads();
        }
        if (tid == 0) {
            float v = sred[0];
            if (v > sbest) { sbest = v; sbidx = c; }  // ascending ci keeps lowest idx on tie
        }
        __syncthreads();
    }

    const int ind = sbidx;
    if (tid == 0) {
        ind_out[n] = (float)ind;
        atomicAdd(&g_bins[ind], 1.0f);
    }

    const float4 e4 = reinterpret_cast<const float4*>(embed + (size_t)ind * D_)[tid];
    reinterpret_cast<float4*>(quant_out + (size_t)n * D_)[tid] = e4;
    float* srowp = g_embed_sum + (size_t)ind * D_ + tid * 4;
    atomicAdd(&srowp[0], x4v.x);
    atomicAdd(&srowp[1], x4v.y);
    atomicAdd(&srowp[2], x4v.z);
    atomicAdd(&srowp[3], x4v.w);
}

// ---------------------------------------------------------------------------
// Kernel 4: new_cluster_size + total (single block)
// ---------------------------------------------------------------------------
__global__ __launch_bounds__(1024)
void cluster_size_kernel(const float* __restrict__ cluster_size,
                         float* __restrict__ ncs_out) {
    const int tid = threadIdx.x;
    float local = 0.0f;
#pragma unroll
    for (int l = 0; l < C_ / 1024; l++) {
        int c = tid + l * 1024;
        float v = cluster_size[c] * DECAY + g_bins[c] * ONE_MINUS_DECAY;
        ncs_out[c] = v;
        local += v;
    }
    __shared__ float red[1024];
    red[tid] = local;
    __syncthreads();
#pragma unroll
    for (int s = 512; s > 0; s >>= 1) {
        if (tid < s) red[tid] += red[tid + s];
        __syncthreads();
    }
    if (tid == 0) g_total = red[0];
}

// ---------------------------------------------------------------------------
// Kernel 5: per-code EMA + normalize. One block per code c, 128 threads.
// ---------------------------------------------------------------------------
__global__ __launch_bounds__(128)
void embed_update_kernel(const float* __restrict__ embed_avg,
                         const float* __restrict__ ncs,
                         float* __restrict__ nea_out,
                         float* __restrict__ ne_out) {
    const int c = blockIdx.x;
    const int tid = threadIdx.x;

    const float total = g_total;
    const float n_cs = ncs[c];
    const float smoothed = (n_cs + EPS_) / (total + (float)C_ * EPS_) * total;
    const float inv_s = 1.0f / smoothed;

    float v[D_ / 128];
    float sumsq = 0.0f;
#pragma unroll
    for (int l = 0; l < D_ / 128; l++) {
        int d = tid + l * 128;
        float nea = embed_avg[(size_t)c * D_ + d] * DECAY +
                    g_embed_sum[(size_t)c * D_ + d] * ONE_MINUS_DECAY;
        nea_out[(size_t)c * D_ + d] = nea;
        float t = nea * inv_s;
        v[l] = t;
        sumsq += t * t;
    }

    __shared__ float red[128];
    red[tid] = sumsq;
    __syncthreads();
#pragma unroll
    for (int s = 64; s > 0; s >>= 1) {
        if (tid < s) red[tid] += red[tid + s];
        __syncthreads();
    }
    float norm = sqrtf(red[0]);
    norm = fmaxf(norm, 1e-12f);
    float inv_n = 1.0f / norm;
#pragma unroll
    for (int l = 0; l < D_ / 128; l++) {
        int d = tid + l * 128;
        ne_out[(size_t)c * D_ + d] = v[l] * inv_n;
    }
}

// ---------------------------------------------------------------------------
// Launch
// ---------------------------------------------------------------------------
extern "C" void kernel_launch(void* const* d_in, const int* in_sizes, int n_in,
                              void* d_out, int out_size) {
    const float* x          = (const float*)d_in[0];  // (16,1024,512)
    const float* embed      = (const float*)d_in[1];  // (1,4096,512)
    const float* cluster_sz = (const float*)d_in[2];  // (1,4096)
    const float* embed_avg  = (const float*)d_in[3];  // (1,4096,512)
    float* out = (float*)d_out;

    float* out_q    = out + OFF_Q;
    float* out_ind  = out + OFF_IND;
    float* out_dist = out + OFF_DIST;
    float* out_ne   = out + OFF_NE;
    float* out_ncs  = out + OFF_NCS;
    float* out_nea  = out + OFF_NEA;

    (void)in_sizes; (void)n_in; (void)out_size;

    zero_scratch_kernel<<<512, 256>>>();

    float* gxt; cudaGetSymbolAddress((void**)&gxt, g_xt);
    float* get; cudaGetSymbolAddress((void**)&get, g_et);
    prep_kernel<<<(NTOT * D_ / 4) / 256, 256>>>(x, gxt);
    prep_kernel<<<(C_ * D_ / 4) / 256, 256>>>(embed, get);

    static bool attr_done = false;
    if (!attr_done) {
        cudaFuncSetAttribute(dist_mma_kernel,
                             cudaFuncAttributeMaxDynamicSharedMemorySize,
                             SMEM_GEMM_BYTES);
        attr_done = true;
    }
    dim3 ggrid(NNT, NMT);   // (16, 128)
    dist_mma_kernel<<<ggrid, 256, SMEM_GEMM_BYTES>>>(gxt, get, out_dist);

    rescue_kernel<<<NTOT, 128>>>(out_dist, x, embed, out_q, out_ind);

    cluster_size_kernel<<<1, 1024>>>(cluster_sz, out_ncs);

    embed_update_kernel<<<C_, 128>>>(embed_avg, out_ncs, out_nea, out_ne);
}

// round 12
// speedup vs baseline: 1.0420x; 1.0420x over previous
#include <cuda_runtime.h>
#include <math.h>
#include <stdint.h>

// Problem constants
#define B_   16
#define N_   1024
#define D_   512
#define C_   4096
#define NTOT (B_ * N_)        // 16384
#define DECAY 0.8f
#define ONE_MINUS_DECAY 0.2f
#define EPS_ 1e-5f

// Output layout (floats), concatenated in reference return order
#define OFF_Q    0ull
#define OFF_IND  (OFF_Q + (unsigned long long)NTOT * D_)
#define OFF_DIST (OFF_IND + NTOT)
#define OFF_NE   (OFF_DIST + (unsigned long long)NTOT * C_)
#define OFF_NCS  (OFF_NE + (unsigned long long)C_ * D_)
#define OFF_NEA  (OFF_NCS + C_)

// GEMM tiling
#define BM 128
#define BN 256
#define BKF 32
#define NNT (C_ / BN)         // 16 n-tiles
#define NMT (NTOT / BM)       // 128 m-tiles

// ---------------------------------------------------------------------------
// Device scratch (static; no runtime allocation allowed)
// ---------------------------------------------------------------------------
__device__ float g_bins[C_];
__device__ float g_embed_sum[(size_t)C_ * D_];
__device__ float g_total;
__device__ float g_xt[(size_t)NTOT * D_];   // tf32-rounded x, K-pair-interleaved
__device__ float g_et[(size_t)C_ * D_];     // tf32-rounded embed, K-pair-interleaved
__device__ float g_pmax[(size_t)NTOT * NNT];  // per-(row, ntile) approx max

// ---------------------------------------------------------------------------
// PTX helpers (base sm_80-level features only)
// ---------------------------------------------------------------------------
__device__ __forceinline__ uint32_t smem_u32(const void* p) {
    uint32_t a;
    asm("{ .reg .u64 t; cvta.to.shared.u64 t, %1; cvt.u32.u64 %0, t; }"
        : "=r"(a) : "l"(p));
    return a;
}
__device__ __forceinline__ void cp_async16(uint32_t dst, const void* src) {
    asm volatile("cp.async.ca.shared.global [%0], [%1], 16;"
                 :: "r"(dst), "l"(src) : "memory");
}
__device__ __forceinline__ void cp_commit() {
    asm volatile("cp.async.commit_group;" ::: "memory");
}
template <int N>
__device__ __forceinline__ void cp_wait() {
    asm volatile("cp.async.wait_group %0;" :: "n"(N) : "memory");
}
__device__ __forceinline__ float tf32_rna(float v) {
    uint32_t o;
    asm("cvt.rna.tf32.f32 %0, %1;" : "=r"(o) : "f"(v));
    return __uint_as_float(o);
}
__device__ __forceinline__ void mma_tf32(float* d, const uint32_t* a,
                                         const uint32_t* b, const float* c) {
    asm volatile(
        "mma.sync.aligned.m16n8k8.row.col.f32.tf32.tf32.f32 "
        "{%0,%1,%2,%3}, {%4,%5,%6,%7}, {%8,%9}, {%10,%11,%12,%13};"
        : "=f"(d[0]), "=f"(d[1]), "=f"(d[2]), "=f"(d[3])
        : "r"(a[0]), "r"(a[1]), "r"(a[2]), "r"(a[3]),
          "r"(b[0]), "r"(b[1]),
          "f"(c[0]), "f"(c[1]), "f"(c[2]), "f"(c[3]));
}
// monotone float <-> uint encoding (for atomicMax on shared)
__device__ __forceinline__ unsigned fenc(float f) {
    unsigned u = __float_as_uint(f);
    return (u & 0x80000000u) ? ~u : (u | 0x80000000u);
}
__device__ __forceinline__ float fdec(unsigned u) {
    unsigned v = (u & 0x80000000u) ? (u & 0x7fffffffu) : ~u;
    return __uint_as_float(v);
}

// ---------------------------------------------------------------------------
// Kernel 0: zero scratch (bins + embed_sum)
// ---------------------------------------------------------------------------
__global__ void zero_scratch_kernel() {
    size_t total = (size_t)C_ * D_ + C_;
    size_t idx = (size_t)blockIdx.x * blockDim.x + threadIdx.x;
    size_t stride = (size_t)gridDim.x * blockDim.x;
    for (size_t i = idx; i < total; i += stride) {
        if (i < (size_t)C_ * D_) g_embed_sum[i] = 0.0f;
        else g_bins[i - (size_t)C_ * D_] = 0.0f;
    }
}

// ---------------------------------------------------------------------------
// Kernel 1: round fp32 -> tf32 (rna) + K-pair-interleave within 8-word groups.
// Element k goes to word  group(k)*8 + 2*(k mod 4) + (k mod 8 >= 4 ? 1 : 0).
// So pairs (k0+q, k0+4+q) land adjacent -> LDS.64 fragment loads in the GEMM.
// ---------------------------------------------------------------------------
__global__ __launch_bounds__(256)
void prep_kernel(const float* __restrict__ in, float* __restrict__ out) {
    size_t i = (size_t)blockIdx.x * 256 + threadIdx.x;   // float4 index
    int n  = (int)(i >> 7);       // 128 float4 per row (D=512)
    int f  = (int)(i & 127);
    int k0 = f * 4;               // multiple of 4: either low or high half of a group
    float4 v = *reinterpret_cast<const float4*>(&in[(size_t)n * D_ + k0]);
    float r0 = tf32_rna(v.x);
    float r1 = tf32_rna(v.y);
    float r2 = tf32_rna(v.z);
    float r3 = tf32_rna(v.w);
    int group = k0 >> 3;
    int odd = (k0 & 4) ? 1 : 0;   // high half -> odd slots
    float* dst = out + (size_t)n * D_ + group * 8 + odd;
    dst[0] = r0;
    dst[2] = r1;
    dst[4] = r2;
    dst[6] = r3;
}

// ---------------------------------------------------------------------------
// Kernel 2: dist GEMM via mma.sync tf32.
// BM=128 BN=256 BK=32, 256 threads, warp grid 2x4, warp tile 64x64.
// 3-stage cp.async pipeline. K-pair-interleaved smem -> LDS.64 fragments,
// explicit fragment double-buffering across ks. ROWSTRIDE=40 (LDS.64
// conflict-free: (g*40 + 2q) mod 64 distinct over the warp).
// Fused per-(row, ntile) max -> g_pmax.
// ---------------------------------------------------------------------------
#define ROWSTRIDE 40
#define A_WORDS (BM * ROWSTRIDE)             // 5120
#define B_WORDS (BN * ROWSTRIDE)             // 10240
#define STAGE_WORDS (A_WORDS + B_WORDS)      // 15360 words = 61440 B
#define NSTAGE 3
#define SMEM_GEMM_BYTES (NSTAGE * STAGE_WORDS * 4 + 512 + 128)

__global__ __launch_bounds__(256, 1)
void dist_mma_kernel(const float* __restrict__ xt,
                     const float* __restrict__ et,
                     float* __restrict__ dist) {
    extern __shared__ float smem[];
    unsigned* smax = reinterpret_cast<unsigned*>(smem + NSTAGE * STAGE_WORDS);
    const uint32_t sbase = smem_u32(smem);
    const int tid = threadIdx.x;
    const int wid = tid >> 5;
    const int lane = tid & 31;
    const int g = lane >> 2;   // 0..7
    const int q = lane & 3;    // 0..3
    const int wm = (wid >> 2) * 64;  // warp m offset (2 warps in m)
    const int wn = (wid & 3) * 64;   // warp n offset (4 warps in n)

    const int ntile = blockIdx.x;
    const int mtile = blockIdx.y;
    const int m0 = mtile * BM;
    const int c0 = ntile * BN;

    if (tid < BM) smax[tid] = 0u;   // enc(-inf) < any enc

    float acc[4][8][4];
#pragma unroll
    for (int mt = 0; mt < 4; mt++)
#pragma unroll
        for (int nt = 0; nt < 8; nt++)
#pragma unroll
            for (int j = 0; j < 4; j++) acc[mt][nt][j] = 0.0f;

    auto load_stage = [&](int kt, int st) {
        const uint32_t abase = sbase + (uint32_t)(st * STAGE_WORDS) * 4;
        const uint32_t bbase = abase + (uint32_t)A_WORDS * 4;
        // A: 128 rows x 8 float4 = 1024 slots, 4 per thread
#pragma unroll
        for (int l = 0; l < 4; l++) {
            int idx = tid + l * 256;
            int row = idx >> 3;
            int kc = (idx & 7) << 2;
            cp_async16(abase + (uint32_t)(row * ROWSTRIDE + kc) * 4,
                       &xt[(size_t)(m0 + row) * D_ + kt * BKF + kc]);
        }
        // B: 256 rows x 8 float4 = 2048 slots, 8 per thread
#pragma unroll
        for (int l = 0; l < 8; l++) {
            int idx = tid + l * 256;
            int row = idx >> 3;
            int kc = (idx & 7) << 2;
            cp_async16(bbase + (uint32_t)(row * ROWSTRIDE + kc) * 4,
                       &et[(size_t)(c0 + row) * D_ + kt * BKF + kc]);
        }
        cp_commit();
    };

    load_stage(0, 0);
    load_stage(1, 1);

    const int NK = D_ / BKF;   // 16
    for (int kt = 0; kt < NK; kt++) {
        if (kt + 1 < NK) cp_wait<1>(); else cp_wait<0>();
        __syncthreads();
        if (kt + 2 < NK) load_stage(kt + 2, (kt + 2) % NSTAGE);

        const int st = kt % NSTAGE;
        const uint32_t* Au = reinterpret_cast<const uint32_t*>(smem + st * STAGE_WORDS);
        const uint32_t* Bu = Au + A_WORDS;

        // Fragment double buffers: pa0 = (a0,a2) row r, pa1 = (a1,a3) row r+8,
        // pb = (b0,b1). Pair words adjacent thanks to K-interleave.
        uint2 pa0[2][4], pa1[2][4], pb[2][8];

        auto load_frag = [&](int ks, int buf) {
            const int kw = ks * 8 + 2 * q;   // word offset within row
#pragma unroll
            for (int mt = 0; mt < 4; mt++) {
                int r = wm + mt * 16 + g;
                pa0[buf][mt] = *reinterpret_cast<const uint2*>(&Au[r * ROWSTRIDE + kw]);
                pa1[buf][mt] = *reinterpret_cast<const uint2*>(&Au[(r + 8) * ROWSTRIDE + kw]);
            }
#pragma unroll
            for (int nt = 0; nt < 8; nt++) {
                int rn = wn + nt * 8 + g;
                pb[buf][nt] = *reinterpret_cast<const uint2*>(&Bu[rn * ROWSTRIDE + kw]);
            }
        };

        load_frag(0, 0);
#pragma unroll
        for (int ks = 0; ks < 4; ks++) {
            const int cur = ks & 1;
            if (ks + 1 < 4) load_frag(ks + 1, cur ^ 1);
#pragma unroll
            for (int mt = 0; mt < 4; mt++) {
                uint32_t a[4] = {pa0[cur][mt].x, pa1[cur][mt].x,
                                 pa0[cur][mt].y, pa1[cur][mt].y};
#pragma unroll
                for (int nt = 0; nt < 8; nt++) {
                    uint32_t b[2] = {pb[cur][nt].x, pb[cur][nt].y};
                    mma_tf32(acc[mt][nt], a, b, acc[mt][nt]);
                }
            }
        }
        __syncthreads();
    }

    // Epilogue: write dist + per-row max (shared atomicMax, enc monotone)
#pragma unroll
    for (int mt = 0; mt < 4; mt++) {
        float mA = -INFINITY, mB = -INFINITY;
#pragma unroll
        for (int nt = 0; nt < 8; nt++) {
            int row = m0 + wm + mt * 16 + g;
            int col = c0 + wn + nt * 8 + 2 * q;
            float2 v01 = make_float2(acc[mt][nt][0], acc[mt][nt][1]);
            float2 v23 = make_float2(acc[mt][nt][2], acc[mt][nt][3]);
            *reinterpret_cast<float2*>(&dist[(size_t)row * C_ + col]) = v01;
            *reinterpret_cast<float2*>(&dist[(size_t)(row + 8) * C_ + col]) = v23;
            mA = fmaxf(mA, fmaxf(v01.x, v01.y));
            mB = fmaxf(mB, fmaxf(v23.x, v23.y));
        }
        atomicMax(&smax[wm + mt * 16 + g], fenc(mA));
        atomicMax(&smax[wm + mt * 16 + 8 + g], fenc(mB));
    }
    __syncthreads();
    if (tid < BM)
        g_pmax[(size_t)(m0 + tid) * NNT + ntile] = fdec(smax[tid]);
}

// ---------------------------------------------------------------------------
// Kernel 3: rescue argmax driven by tile maxes + exact recompute of
//           near-max candidates + gather quantize + scatter embed_sum/bins.
// One block per row n, 128 threads.
// ---------------------------------------------------------------------------
#define MARGIN 3e-3f
#define MAXCAND 32

__global__ __launch_bounds__(128)
void rescue_kernel(const float* __restrict__ dist,
                   const float* __restrict__ x,
                   const float* __restrict__ embed,
                   float* __restrict__ quant_out,
                   float* __restrict__ ind_out) {
    const int n = blockIdx.x;
    const int tid = threadIdx.x;
    __shared__ float spm[NNT];
    __shared__ float sred[128];
    __shared__ int scand[MAXCAND];
    __shared__ int scount;
    __shared__ float sM;
    __shared__ float sbest;
    __shared__ int sbidx;

    if (tid < NNT) spm[tid] = g_pmax[(size_t)n * NNT + tid];
    if (tid == 0) { scount = 0; sbest = -INFINITY; sbidx = 0; }
    __syncthreads();
    if (tid == 0) {
        float M = -INFINITY;
#pragma unroll
        for (int t = 0; t < NNT; t++) M = fmaxf(M, spm[t]);
        sM = M;
    }
    __syncthreads();
    const float thresh = sM - MARGIN;

    const float* drow = dist + (size_t)n * C_;
#pragma unroll 1
    for (int t = 0; t < NNT; t++) {
        if (spm[t] >= thresh) {
#pragma unroll
            for (int i = 0; i < 2; i++) {
                int c = t * BN + i * 128 + tid;
                if (drow[c] >= thresh) {
                    int p = atomicAdd(&scount, 1);
                    if (p < MAXCAND) scand[p] = c;
                }
            }
        }
    }
    __syncthreads();
    int ncand = min(scount, MAXCAND);
    if (tid == 0 && ncand > 1) {
        // insertion sort ascending (first-index tie-break like jnp.argmax)
        for (int i = 1; i < ncand; i++) {
            int key = scand[i];
            int j = i - 1;
            while (j >= 0 && scand[j] > key) { scand[j + 1] = scand[j]; j--; }
            scand[j + 1] = key;
        }
    }
    __syncthreads();

    const float4 x4v = reinterpret_cast<const float4*>(x + (size_t)n * D_)[tid];

    for (int ci = 0; ci < ncand; ci++) {
        const int c = scand[ci];
        const float4 e4 = reinterpret_cast<const float4*>(embed + (size_t)c * D_)[tid];
        float p = x4v.x * e4.x + x4v.y * e4.y + x4v.z * e4.z + x4v.w * e4.w;
        sred[tid] = p;
        __syncthreads();
#pragma unroll
        for (int s = 64; s > 0; s >>= 1) {
            if (tid < s) sred[tid] += sred[tid + s];
            __syncthreads();
        }
        if (tid == 0) {
            float v = sred[0];
            if (v > sbest) { sbest = v; sbidx = c; }  // ascending ci keeps lowest idx on tie
        }
        __syncthreads();
    }

    const int ind = sbidx;
    if (tid == 0) {
        ind_out[n] = (float)ind;
        atomicAdd(&g_bins[ind], 1.0f);
    }

    const float4 e4 = reinterpret_cast<const float4*>(embed + (size_t)ind * D_)[tid];
    reinterpret_cast<float4*>(quant_out + (size_t)n * D_)[tid] = e4;
    float* srowp = g_embed_sum + (size_t)ind * D_ + tid * 4;
    atomicAdd(&srowp[0], x4v.x);
    atomicAdd(&srowp[1], x4v.y);
    atomicAdd(&srowp[2], x4v.z);
    atomicAdd(&srowp[3], x4v.w);
}

// ---------------------------------------------------------------------------
// Kernel 4: new_cluster_size + total (single block)
// ---------------------------------------------------------------------------
__global__ __launch_bounds__(1024)
void cluster_size_kernel(const float* __restrict__ cluster_size,
                         float* __restrict__ ncs_out) {
    const int tid = threadIdx.x;
    float local = 0.0f;
#pragma unroll
    for (int l = 0; l < C_ / 1024; l++) {
        int c = tid + l * 1024;
        float v = cluster_size[c] * DECAY + g_bins[c] * ONE_MINUS_DECAY;
        ncs_out[c] = v;
        local += v;
    }
    __shared__ float red[1024];
    red[tid] = local;
    __syncthreads();
#pragma unroll
    for (int s = 512; s > 0; s >>= 1) {
        if (tid < s) red[tid] += red[tid + s];
        __syncthreads();
    }
    if (tid == 0) g_total = red[0];
}

// ---------------------------------------------------------------------------
// Kernel 5: per-code EMA + normalize. One block per code c, 128 threads.
// ---------------------------------------------------------------------------
__global__ __launch_bounds__(128)
void embed_update_kernel(const float* __restrict__ embed_avg,
                         const float* __restrict__ ncs,
                         float* __restrict__ nea_out,
                         float* __restrict__ ne_out) {
    const int c = blockIdx.x;
    const int tid = threadIdx.x;

    const float total = g_total;
    const float n_cs = ncs[c];
    const float smoothed = (n_cs + EPS_) / (total + (float)C_ * EPS_) * total;
    const float inv_s = 1.0f / smoothed;

    float v[D_ / 128];
    float sumsq = 0.0f;
#pragma unroll
    for (int l = 0; l < D_ / 128; l++) {
        int d = tid + l * 128;
        float nea = embed_avg[(size_t)c * D_ + d] * DECAY +
                    g_embed_sum[(size_t)c * D_ + d] * ONE_MINUS_DECAY;
        nea_out[(size_t)c * D_ + d] = nea;
        float t = nea * inv_s;
        v[l] = t;
        sumsq += t * t;
    }

    __shared__ float red[128];
    red[tid] = sumsq;
    __syncthreads();
#pragma unroll
    for (int s = 64; s > 0; s >>= 1) {
        if (tid < s) red[tid] += red[tid + s];
        __syncthreads();
    }
    float norm = sqrtf(red[0]);
    norm = fmaxf(norm, 1e-12f);
    float inv_n = 1.0f / norm;
#pragma unroll
    for (int l = 0; l < D_ / 128; l++) {
        int d = tid + l * 128;
        ne_out[(size_t)c * D_ + d] = v[l] * inv_n;
    }
}

// ---------------------------------------------------------------------------
// Launch
// ---------------------------------------------------------------------------
extern "C" void kernel_launch(void* const* d_in, const int* in_sizes, int n_in,
                              void* d_out, int out_size) {
    const float* x          = (const float*)d_in[0];  // (16,1024,512)
    const float* embed      = (const float*)d_in[1];  // (1,4096,512)
    const float* cluster_sz = (const float*)d_in[2];  // (1,4096)
    const float* embed_avg  = (const float*)d_in[3];  // (1,4096,512)
    float* out = (float*)d_out;

    float* out_q    = out + OFF_Q;
    float* out_ind  = out + OFF_IND;
    float* out_dist = out + OFF_DIST;
    float* out_ne   = out + OFF_NE;
    float* out_ncs  = out + OFF_NCS;
    float* out_nea  = out + OFF_NEA;

    (void)in_sizes; (void)n_in; (void)out_size;

    zero_scratch_kernel<<<512, 256>>>();

    float* gxt; cudaGetSymbolAddress((void**)&gxt, g_xt);
    float* get; cudaGetSymbolAddress((void**)&get, g_et);
    prep_kernel<<<(NTOT * D_ / 4) / 256, 256>>>(x, gxt);
    prep_kernel<<<(C_ * D_ / 4) / 256, 256>>>(embed, get);

    static bool attr_done = false;
    if (!attr_done) {
        cudaFuncSetAttribute(dist_mma_kernel,
                             cudaFuncAttributeMaxDynamicSharedMemorySize,
                             SMEM_GEMM_BYTES);
        attr_done = true;
    }
    dim3 ggrid(NNT, NMT);   // (16, 128)
    dist_mma_kernel<<<ggrid, 256, SMEM_GEMM_BYTES>>>(gxt, get, out_dist);

    rescue_kernel<<<NTOT, 128>>>(out_dist, x, embed, out_q, out_ind);

    cluster_size_kernel<<<1, 1024>>>(cluster_sz, out_ncs);

    embed_update_kernel<<<C_, 128>>>(embed_avg, out_ncs, out_nea, out_ne);
}

// round 15
// speedup vs baseline: 1.0724x; 1.0292x over previous
#include <cuda_runtime.h>
#include <math.h>
#include <stdint.h>

// Problem constants
#define B_   16
#define N_   1024
#define D_   512
#define C_   4096
#define NTOT (B_ * N_)        // 16384
#define DECAY 0.8f
#define ONE_MINUS_DECAY 0.2f
#define EPS_ 1e-5f

// Output layout (floats), concatenated in reference return order
#define OFF_Q    0ull
#define OFF_IND  (OFF_Q + (unsigned long long)NTOT * D_)
#define OFF_DIST (OFF_IND + NTOT)
#define OFF_NE   (OFF_DIST + (unsigned long long)NTOT * C_)
#define OFF_NCS  (OFF_NE + (unsigned long long)C_ * D_)
#define OFF_NEA  (OFF_NCS + C_)

// GEMM tiling
#define BM 128
#define BN 256
#define BKF 32
#define NNT (C_ / BN)         // 16 n-tiles
#define NMT (NTOT / BM)       // 128 m-tiles

// ---------------------------------------------------------------------------
// Device scratch (static; no runtime allocation allowed)
// ---------------------------------------------------------------------------
__device__ float g_bins[C_];
__device__ float g_embed_sum[(size_t)C_ * D_];
__device__ float g_total;
__device__ float g_xt[(size_t)NTOT * D_];   // tf32-rounded x
__device__ float g_et[(size_t)C_ * D_];     // tf32-rounded embed
__device__ float g_pmax[(size_t)NTOT * NNT];  // per-(row, ntile) approx max

// ---------------------------------------------------------------------------
// PTX helpers (base sm_80-level features only)
// ---------------------------------------------------------------------------
__device__ __forceinline__ uint32_t smem_u32(const void* p) {
    uint32_t a;
    asm("{ .reg .u64 t; cvta.to.shared.u64 t, %1; cvt.u32.u64 %0, t; }"
        : "=r"(a) : "l"(p));
    return a;
}
__device__ __forceinline__ void cp_async16(uint32_t dst, const void* src) {
    asm volatile("cp.async.ca.shared.global [%0], [%1], 16;"
                 :: "r"(dst), "l"(src) : "memory");
}
__device__ __forceinline__ void cp_commit() {
    asm volatile("cp.async.commit_group;" ::: "memory");
}
template <int N>
__device__ __forceinline__ void cp_wait() {
    asm volatile("cp.async.wait_group %0;" :: "n"(N) : "memory");
}
__device__ __forceinline__ float tf32_rna(float v) {
    uint32_t o;
    asm("cvt.rna.tf32.f32 %0, %1;" : "=r"(o) : "f"(v));
    return __uint_as_float(o);
}
__device__ __forceinline__ void mma_tf32(float* d, const uint32_t* a,
                                         const uint32_t* b, const float* c) {
    asm volatile(
        "mma.sync.aligned.m16n8k8.row.col.f32.tf32.tf32.f32 "
        "{%0,%1,%2,%3}, {%4,%5,%6,%7}, {%8,%9}, {%10,%11,%12,%13};"
        : "=f"(d[0]), "=f"(d[1]), "=f"(d[2]), "=f"(d[3])
        : "r"(a[0]), "r"(a[1]), "r"(a[2]), "r"(a[3]),
          "r"(b[0]), "r"(b[1]),
          "f"(c[0]), "f"(c[1]), "f"(c[2]), "f"(c[3]));
}
// monotone float <-> uint encoding (for atomicMax on shared)
__device__ __forceinline__ unsigned fenc(float f) {
    unsigned u = __float_as_uint(f);
    return (u & 0x80000000u) ? ~u : (u | 0x80000000u);
}
__device__ __forceinline__ float fdec(unsigned u) {
    unsigned v = (u & 0x80000000u) ? (u & 0x7fffffffu) : ~u;
    return __uint_as_float(v);
}

// ---------------------------------------------------------------------------
// Kernel 1: fused prep (x -> g_xt, embed -> g_et, tf32 rna) + scratch zeroing.
// Block partition:
//   [0, XB)           : x prep (one float4 per thread)
//   [XB, XB+EB)       : embed prep
//   [XB+EB, XB+EB+ZB) : zero g_embed_sum/g_bins/g_total (float4 stores)
// ---------------------------------------------------------------------------
#define XB (NTOT * D_ / 4 / 256)     // 8192
#define EB (C_ * D_ / 4 / 256)       // 2048
#define ZTOT ((C_ * D_ + C_) / 4)    // 525312 float4 (embed_sum then bins)
#define ZB ((ZTOT + 255) / 256)      // 2053

__global__ __launch_bounds__(256)
void prep_zero_kernel(const float* __restrict__ x, const float* __restrict__ embed) {
    int b = blockIdx.x;
    if (b < XB) {
        size_t i = (size_t)b * 256 + threadIdx.x;
        float4 v = reinterpret_cast<const float4*>(x)[i];
        v.x = tf32_rna(v.x); v.y = tf32_rna(v.y);
        v.z = tf32_rna(v.z); v.w = tf32_rna(v.w);
        reinterpret_cast<float4*>(g_xt)[i] = v;
    } else if (b < XB + EB) {
        size_t i = (size_t)(b - XB) * 256 + threadIdx.x;
        float4 v = reinterpret_cast<const float4*>(embed)[i];
        v.x = tf32_rna(v.x); v.y = tf32_rna(v.y);
        v.z = tf32_rna(v.z); v.w = tf32_rna(v.w);
        reinterpret_cast<float4*>(g_et)[i] = v;
    } else {
        size_t i = (size_t)(b - XB - EB) * 256 + threadIdx.x;
        if (i < ZTOT) {
            // g_embed_sum (C*D floats) followed logically by g_bins (C floats)
            float4 z = make_float4(0.f, 0.f, 0.f, 0.f);
            if (i < (size_t)C_ * D_ / 4)
                reinterpret_cast<float4*>(g_embed_sum)[i] = z;
            else
                reinterpret_cast<float4*>(g_bins)[i - (size_t)C_ * D_ / 4] = z;
        }
        if (b == XB + EB && threadIdx.x == 0) g_total = 0.0f;
    }
}

// ---------------------------------------------------------------------------
// Kernel 2: dist GEMM via mma.sync tf32.  (round-9 champion, verbatim)
// BM=128 BN=256 BK=32, 256 threads, warp grid 2x4, warp tile 64x64.
// 3-stage cp.async pipeline. Fused per-(row, ntile) max -> g_pmax.
// Smem per stage: A [128][36] + B [256][36] floats (stride 36 conflict-free).
// ---------------------------------------------------------------------------
#define ROWSTRIDE 36
#define A_WORDS (BM * ROWSTRIDE)             // 4608
#define B_WORDS (BN * ROWSTRIDE)             // 9216
#define STAGE_WORDS (A_WORDS + B_WORDS)      // 13824 words = 55296 B
#define NSTAGE 3
#define SMEM_GEMM_BYTES (NSTAGE * STAGE_WORDS * 4 + 512 + 128)  // + smax + pad

__global__ __launch_bounds__(256, 1)
void dist_mma_kernel(const float* __restrict__ xt,
                     const float* __restrict__ et,
                     float* __restrict__ dist) {
    extern __shared__ float smem[];
    unsigned* smax = reinterpret_cast<unsigned*>(smem + NSTAGE * STAGE_WORDS);
    const uint32_t sbase = smem_u32(smem);
    const int tid = threadIdx.x;
    const int wid = tid >> 5;
    const int lane = tid & 31;
    const int g = lane >> 2;   // 0..7
    const int q = lane & 3;    // 0..3
    const int wm = (wid >> 2) * 64;  // warp m offset (2 warps in m)
    const int wn = (wid & 3) * 64;   // warp n offset (4 warps in n)

    const int ntile = blockIdx.x;
    const int mtile = blockIdx.y;
    const int m0 = mtile * BM;
    const int c0 = ntile * BN;

    if (tid < BM) smax[tid] = 0u;   // enc(-inf) < any enc

    float acc[4][8][4];
#pragma unroll
    for (int mt = 0; mt < 4; mt++)
#pragma unroll
        for (int nt = 0; nt < 8; nt++)
#pragma unroll
            for (int j = 0; j < 4; j++) acc[mt][nt][j] = 0.0f;

    auto load_stage = [&](int kt, int st) {
        const uint32_t abase = sbase + (uint32_t)(st * STAGE_WORDS) * 4;
        const uint32_t bbase = abase + (uint32_t)A_WORDS * 4;
        // A: 128 rows x 8 float4 = 1024 slots, 4 per thread
#pragma unroll
        for (int l = 0; l < 4; l++) {
            int idx = tid + l * 256;
            int row = idx >> 3;
            int kc = (idx & 7) << 2;
            cp_async16(abase + (uint32_t)(row * ROWSTRIDE + kc) * 4,
                       &xt[(size_t)(m0 + row) * D_ + kt * BKF + kc]);
        }
        // B: 256 rows x 8 float4 = 2048 slots, 8 per thread
#pragma unroll
        for (int l = 0; l < 8; l++) {
            int idx = tid + l * 256;
            int row = idx >> 3;
            int kc = (idx & 7) << 2;
            cp_async16(bbase + (uint32_t)(row * ROWSTRIDE + kc) * 4,
                       &et[(size_t)(c0 + row) * D_ + kt * BKF + kc]);
        }
        cp_commit();
    };

    load_stage(0, 0);
    load_stage(1, 1);

    const int NK = D_ / BKF;   // 16
    for (int kt = 0; kt < NK; kt++) {
        if (kt + 1 < NK) cp_wait<1>(); else cp_wait<0>();
        __syncthreads();
        if (kt + 2 < NK) load_stage(kt + 2, (kt + 2) % NSTAGE);

        const int st = kt % NSTAGE;
        const uint32_t* Au = reinterpret_cast<const uint32_t*>(smem + st * STAGE_WORDS);
        const uint32_t* Bu = Au + A_WORDS;

#pragma unroll
        for (int ks = 0; ks < 4; ks++) {
            const int k0 = ks * 8;
            uint32_t a[4][4], b[8][2];
#pragma unroll
            for (int mt = 0; mt < 4; mt++) {
                int r = wm + mt * 16 + g;
                a[mt][0] = Au[r * ROWSTRIDE + k0 + q];
                a[mt][1] = Au[(r + 8) * ROWSTRIDE + k0 + q];
                a[mt][2] = Au[r * ROWSTRIDE + k0 + 4 + q];
                a[mt][3] = Au[(r + 8) * ROWSTRIDE + k0 + 4 + q];
            }
#pragma unroll
            for (int nt = 0; nt < 8; nt++) {
                int rn = wn + nt * 8 + g;
                b[nt][0] = Bu[rn * ROWSTRIDE + k0 + q];
                b[nt][1] = Bu[rn * ROWSTRIDE + k0 + 4 + q];
            }
#pragma unroll
            for (int mt = 0; mt < 4; mt++)
#pragma unroll
                for (int nt = 0; nt < 8; nt++)
                    mma_tf32(acc[mt][nt], a[mt], b[nt], acc[mt][nt]);
        }
    }
    __syncthreads();

    // Epilogue: write dist + per-row max (shared atomicMax, enc monotone)
#pragma unroll
    for (int mt = 0; mt < 4; mt++) {
        float mA = -INFINITY, mB = -INFINITY;
#pragma unroll
        for (int nt = 0; nt < 8; nt++) {
            int row = m0 + wm + mt * 16 + g;
            int col = c0 + wn + nt * 8 + 2 * q;
            float2 v01 = make_float2(acc[mt][nt][0], acc[mt][nt][1]);
            float2 v23 = make_float2(acc[mt][nt][2], acc[mt][nt][3]);
            *reinterpret_cast<float2*>(&dist[(size_t)row * C_ + col]) = v01;
            *reinterpret_cast<float2*>(&dist[(size_t)(row + 8) * C_ + col]) = v23;
            mA = fmaxf(mA, fmaxf(v01.x, v01.y));
            mB = fmaxf(mB, fmaxf(v23.x, v23.y));
        }
        atomicMax(&smax[wm + mt * 16 + g], fenc(mA));
        atomicMax(&smax[wm + mt * 16 + 8 + g], fenc(mB));
    }
    __syncthreads();
    if (tid < BM)
        g_pmax[(size_t)(m0 + tid) * NNT + ntile] = fdec(smax[tid]);
}

// ---------------------------------------------------------------------------
// Kernel 3: rescue argmax driven by tile maxes + exact recompute of
//           near-max candidates + gather quantize + scatter embed_sum/bins.
// One block per row n, 128 threads.
// ---------------------------------------------------------------------------
#define MARGIN 3e-3f
#define MAXCAND 32

__global__ __launch_bounds__(128)
void rescue_kernel(const float* __restrict__ dist,
                   const float* __restrict__ x,
                   const float* __restrict__ embed,
                   float* __restrict__ quant_out,
                   float* __restrict__ ind_out) {
    const int n = blockIdx.x;
    const int tid = threadIdx.x;
    __shared__ float spm[NNT];
    __shared__ float sred[128];
    __shared__ int scand[MAXCAND];
    __shared__ int scount;
    __shared__ float sM;
    __shared__ float sbest;
    __shared__ int sbidx;

    if (tid < NNT) spm[tid] = g_pmax[(size_t)n * NNT + tid];
    if (tid == 0) { scount = 0; sbest = -INFINITY; sbidx = 0; }
    __syncthreads();
    if (tid == 0) {
        float M = -INFINITY;
#pragma unroll
        for (int t = 0; t < NNT; t++) M = fmaxf(M, spm[t]);
        sM = M;
    }
    __syncthreads();
    const float thresh = sM - MARGIN;

    const float* drow = dist + (size_t)n * C_;
#pragma unroll 1
    for (int t = 0; t < NNT; t++) {
        if (spm[t] >= thresh) {
#pragma unroll
            for (int i = 0; i < 2; i++) {
                int c = t * BN + i * 128 + tid;
                if (drow[c] >= thresh) {
                    int p = atomicAdd(&scount, 1);
                    if (p < MAXCAND) scand[p] = c;
                }
            }
        }
    }
    __syncthreads();
    int ncand = min(scount, MAXCAND);
    if (tid == 0 && ncand > 1) {
        // insertion sort ascending (first-index tie-break like jnp.argmax)
        for (int i = 1; i < ncand; i++) {
            int key = scand[i];
            int j = i - 1;
            while (j >= 0 && scand[j] > key) { scand[j + 1] = scand[j]; j--; }
            scand[j + 1] = key;
        }
    }
    __syncthreads();

    const float4 x4v = reinterpret_cast<const float4*>(x + (size_t)n * D_)[tid];

    for (int ci = 0; ci < ncand; ci++) {
        const int c = scand[ci];
        const float4 e4 = reinterpret_cast<const float4*>(embed + (size_t)c * D_)[tid];
        float p = x4v.x * e4.x + x4v.y * e4.y + x4v.z * e4.z + x4v.w * e4.w;
        sred[tid] = p;
        __syncthreads();
#pragma unroll
        for (int s = 64; s > 0; s >>= 1) {
            if (tid < s) sred[tid] += sred[tid + s];
            __syncthreads();
        }
        if (tid == 0) {
            float v = sred[0];
            if (v > sbest) { sbest = v; sbidx = c; }  // ascending ci keeps lowest idx on tie
        }
        __syncthreads();
    }

    const int ind = sbidx;
    if (tid == 0) {
        ind_out[n] = (float)ind;
        atomicAdd(&g_bins[ind], 1.0f);
    }

    const float4 e4 = reinterpret_cast<const float4*>(embed + (size_t)ind * D_)[tid];
    reinterpret_cast<float4*>(quant_out + (size_t)n * D_)[tid] = e4;
    float* srowp = g_embed_sum + (size_t)ind * D_ + tid * 4;
    atomicAdd(&srowp[0], x4v.x);
    atomicAdd(&srowp[1], x4v.y);
    atomicAdd(&srowp[2], x4v.z);
    atomicAdd(&srowp[3], x4v.w);
}

// ---------------------------------------------------------------------------
// Kernel 4: new_cluster_size + total (parallel; g_total pre-zeroed in prep)
// 4 blocks x 256 threads, 4 elements each.
// ---------------------------------------------------------------------------
__global__ __launch_bounds__(256)
void cluster_size_kernel(const float* __restrict__ cluster_size,
                         float* __restrict__ ncs_out) {
    const int base = blockIdx.x * 1024 + threadIdx.x * 4;
    float4 cs = *reinterpret_cast<const float4*>(&cluster_size[base]);
    float4 bn = *reinterpret_cast<const float4*>(&g_bins[base]);
    float4 v;
    v.x = cs.x * DECAY + bn.x * ONE_MINUS_DECAY;
    v.y = cs.y * DECAY + bn.y * ONE_MINUS_DECAY;
    v.z = cs.z * DECAY + bn.z * ONE_MINUS_DECAY;
    v.w = cs.w * DECAY + bn.w * ONE_MINUS_DECAY;
    *reinterpret_cast<float4*>(&ncs_out[base]) = v;
    float local = v.x + v.y + v.z + v.w;

    __shared__ float red[256];
    red[threadIdx.x] = local;
    __syncthreads();
#pragma unroll
    for (int s = 128; s > 0; s >>= 1) {
        if (threadIdx.x < s) red[threadIdx.x] += red[threadIdx.x + s];
        __syncthreads();
    }
    if (threadIdx.x == 0) atomicAdd(&g_total, red[0]);
}

// ---------------------------------------------------------------------------
// Kernel 5: per-code EMA + normalize. One block per code c, 128 threads.
// ---------------------------------------------------------------------------
__global__ __launch_bounds__(128)
void embed_update_kernel(const float* __restrict__ embed_avg,
                         const float* __restrict__ ncs,
                         float* __restrict__ nea_out,
                         float* __restrict__ ne_out) {
    const int c = blockIdx.x;
    const int tid = threadIdx.x;

    const float total = g_total;
    const float n_cs = ncs[c];
    const float smoothed = (n_cs + EPS_) / (total + (float)C_ * EPS_) * total;
    const float inv_s = 1.0f / smoothed;

    float v[D_ / 128];
    float sumsq = 0.0f;
#pragma unroll
    for (int l = 0; l < D_ / 128; l++) {
        int d = tid + l * 128;
        float nea = embed_avg[(size_t)c * D_ + d] * DECAY +
                    g_embed_sum[(size_t)c * D_ + d] * ONE_MINUS_DECAY;
        nea_out[(size_t)c * D_ + d] = nea;
        float t = nea * inv_s;
        v[l] = t;
        sumsq += t * t;
    }

    __shared__ float red[128];
    red[tid] = sumsq;
    __syncthreads();
#pragma unroll
    for (int s = 64; s > 0; s >>= 1) {
        if (tid < s) red[tid] += red[tid + s];
        __syncthreads();
    }
    float norm = sqrtf(red[0]);
    norm = fmaxf(norm, 1e-12f);
    float inv_n = 1.0f / norm;
#pragma unroll
    for (int l = 0; l < D_ / 128; l++) {
        int d = tid + l * 128;
        ne_out[(size_t)c * D_ + d] = v[l] * inv_n;
    }
}

// ---------------------------------------------------------------------------
// Launch
// ---------------------------------------------------------------------------
extern "C" void kernel_launch(void* const* d_in, const int* in_sizes, int n_in,
                              void* d_out, int out_size) {
    const float* x          = (const float*)d_in[0];  // (16,1024,512)
    const float* embed      = (const float*)d_in[1];  // (1,4096,512)
    const float* cluster_sz = (const float*)d_in[2];  // (1,4096)
    const float* embed_avg  = (const float*)d_in[3];  // (1,4096,512)
    float* out = (float*)d_out;

    float* out_q    = out + OFF_Q;
    float* out_ind  = out + OFF_IND;
    float* out_dist = out + OFF_DIST;
    float* out_ne   = out + OFF_NE;
    float* out_ncs  = out + OFF_NCS;
    float* out_nea  = out + OFF_NEA;

    (void)in_sizes; (void)n_in; (void)out_size;

    float* gxt; cudaGetSymbolAddress((void**)&gxt, g_xt);
    float* get; cudaGetSymbolAddress((void**)&get, g_et);

    prep_zero_kernel<<<XB + EB + ZB, 256>>>(x, embed);

    static bool attr_done = false;
    if (!attr_done) {
        cudaFuncSetAttribute(dist_mma_kernel,
                             cudaFuncAttributeMaxDynamicSharedMemorySize,
                             SMEM_GEMM_BYTES);
        attr_done = true;
    }
    dim3 ggrid(NNT, NMT);   // (16, 128)
    dist_mma_kernel<<<ggrid, 256, SMEM_GEMM_BYTES>>>(gxt, get, out_dist);

    rescue_kernel<<<NTOT, 128>>>(out_dist, x, embed, out_q, out_ind);

    cluster_size_kernel<<<4, 256>>>(cluster_sz, out_ncs);

    embed_update_kernel<<<C_, 128>>>(embed_avg, out_ncs, out_nea, out_ne);
}

// round 16
// speedup vs baseline: 1.1101x; 1.0352x over previous
#include <cuda_runtime.h>
#include <math.h>
#include <stdint.h>

// Problem constants
#define B_   16
#define N_   1024
#define D_   512
#define C_   4096
#define NTOT (B_ * N_)        // 16384
#define DECAY 0.8f
#define ONE_MINUS_DECAY 0.2f
#define EPS_ 1e-5f

// Output layout (floats), concatenated in reference return order
#define OFF_Q    0ull
#define OFF_IND  (OFF_Q + (unsigned long long)NTOT * D_)
#define OFF_DIST (OFF_IND + NTOT)
#define OFF_NE   (OFF_DIST + (unsigned long long)NTOT * C_)
#define OFF_NCS  (OFF_NE + (unsigned long long)C_ * D_)
#define OFF_NEA  (OFF_NCS + C_)

// GEMM tiling
#define BM 128
#define BN 256
#define BKF 32
#define NNT (C_ / BN)         // 16 n-tiles
#define NMT (NTOT / BM)       // 128 m-tiles

// Truncation-bias correction: HW reads fp32 as tf32 by dropping mantissa bits
// (truncate toward zero). Mean relative shrink per operand = 2^-11 * E[1/m]
// (log-uniform mantissa) = 3.52e-4; per product = 7.04e-4.
#define BIAS_CORR 1.000704f

// ---------------------------------------------------------------------------
// Device scratch (static; no runtime allocation allowed)
// ---------------------------------------------------------------------------
__device__ float g_bins[C_];
__device__ float g_embed_sum[(size_t)C_ * D_];
__device__ float g_total;
__device__ float g_pmax[(size_t)NTOT * NNT];  // per-(row, ntile) approx max

// ---------------------------------------------------------------------------
// PTX helpers (base sm_80-level features only)
// ---------------------------------------------------------------------------
__device__ __forceinline__ uint32_t smem_u32(const void* p) {
    uint32_t a;
    asm("{ .reg .u64 t; cvta.to.shared.u64 t, %1; cvt.u32.u64 %0, t; }"
        : "=r"(a) : "l"(p));
    return a;
}
__device__ __forceinline__ void cp_async16(uint32_t dst, const void* src) {
    asm volatile("cp.async.ca.shared.global [%0], [%1], 16;"
                 :: "r"(dst), "l"(src) : "memory");
}
__device__ __forceinline__ void cp_commit() {
    asm volatile("cp.async.commit_group;" ::: "memory");
}
template <int N>
__device__ __forceinline__ void cp_wait() {
    asm volatile("cp.async.wait_group %0;" :: "n"(N) : "memory");
}
__device__ __forceinline__ void mma_tf32(float* d, const uint32_t* a,
                                         const uint32_t* b, const float* c) {
    asm volatile(
        "mma.sync.aligned.m16n8k8.row.col.f32.tf32.tf32.f32 "
        "{%0,%1,%2,%3}, {%4,%5,%6,%7}, {%8,%9}, {%10,%11,%12,%13};"
        : "=f"(d[0]), "=f"(d[1]), "=f"(d[2]), "=f"(d[3])
        : "r"(a[0]), "r"(a[1]), "r"(a[2]), "r"(a[3]),
          "r"(b[0]), "r"(b[1]),
          "f"(c[0]), "f"(c[1]), "f"(c[2]), "f"(c[3]));
}
// monotone float <-> uint encoding (for atomicMax on shared)
__device__ __forceinline__ unsigned fenc(float f) {
    unsigned u = __float_as_uint(f);
    return (u & 0x80000000u) ? ~u : (u | 0x80000000u);
}
__device__ __forceinline__ float fdec(unsigned u) {
    unsigned v = (u & 0x80000000u) ? (u & 0x7fffffffu) : ~u;
    return __uint_as_float(v);
}

// ---------------------------------------------------------------------------
// Kernel 1: zero scratch (g_embed_sum, g_bins, g_total), float4 stores
// ---------------------------------------------------------------------------
#define ZTOT ((C_ * D_ + C_) / 4)    // 525312 float4
#define ZB ((ZTOT + 255) / 256)      // 2053

__global__ __launch_bounds__(256)
void zero_kernel() {
    size_t i = (size_t)blockIdx.x * 256 + threadIdx.x;
    if (i < ZTOT) {
        float4 z = make_float4(0.f, 0.f, 0.f, 0.f);
        if (i < (size_t)C_ * D_ / 4)
            reinterpret_cast<float4*>(g_embed_sum)[i] = z;
        else
            reinterpret_cast<float4*>(g_bins)[i - (size_t)C_ * D_ / 4] = z;
    }
    if (blockIdx.x == 0 && threadIdx.x == 0) g_total = 0.0f;
}

// ---------------------------------------------------------------------------
// Kernel 2: dist GEMM via mma.sync tf32, raw fp32 operands (HW truncation)
// with epilogue bias correction.  Structure = round-9 champion:
// BM=128 BN=256 BK=32, 256 threads, warp grid 2x4, warp tile 64x64,
// 3-stage cp.async pipeline, fused per-(row, ntile) max -> g_pmax.
// Smem per stage: A [128][36] + B [256][36] floats (stride 36 conflict-free).
// ---------------------------------------------------------------------------
#define ROWSTRIDE 36
#define A_WORDS (BM * ROWSTRIDE)             // 4608
#define B_WORDS (BN * ROWSTRIDE)             // 9216
#define STAGE_WORDS (A_WORDS + B_WORDS)      // 13824 words = 55296 B
#define NSTAGE 3
#define SMEM_GEMM_BYTES (NSTAGE * STAGE_WORDS * 4 + 512 + 128)  // + smax + pad

__global__ __launch_bounds__(256, 1)
void dist_mma_kernel(const float* __restrict__ xt,
                     const float* __restrict__ et,
                     float* __restrict__ dist) {
    extern __shared__ float smem[];
    unsigned* smax = reinterpret_cast<unsigned*>(smem + NSTAGE * STAGE_WORDS);
    const uint32_t sbase = smem_u32(smem);
    const int tid = threadIdx.x;
    const int wid = tid >> 5;
    const int lane = tid & 31;
    const int g = lane >> 2;   // 0..7
    const int q = lane & 3;    // 0..3
    const int wm = (wid >> 2) * 64;  // warp m offset (2 warps in m)
    const int wn = (wid & 3) * 64;   // warp n offset (4 warps in n)

    const int ntile = blockIdx.x;
    const int mtile = blockIdx.y;
    const int m0 = mtile * BM;
    const int c0 = ntile * BN;

    if (tid < BM) smax[tid] = 0u;   // enc(-inf) < any enc

    float acc[4][8][4];
#pragma unroll
    for (int mt = 0; mt < 4; mt++)
#pragma unroll
        for (int nt = 0; nt < 8; nt++)
#pragma unroll
            for (int j = 0; j < 4; j++) acc[mt][nt][j] = 0.0f;

    auto load_stage = [&](int kt, int st) {
        const uint32_t abase = sbase + (uint32_t)(st * STAGE_WORDS) * 4;
        const uint32_t bbase = abase + (uint32_t)A_WORDS * 4;
        // A: 128 rows x 8 float4 = 1024 slots, 4 per thread
#pragma unroll
        for (int l = 0; l < 4; l++) {
            int idx = tid + l * 256;
            int row = idx >> 3;
            int kc = (idx & 7) << 2;
            cp_async16(abase + (uint32_t)(row * ROWSTRIDE + kc) * 4,
                       &xt[(size_t)(m0 + row) * D_ + kt * BKF + kc]);
        }
        // B: 256 rows x 8 float4 = 2048 slots, 8 per thread
#pragma unroll
        for (int l = 0; l < 8; l++) {
            int idx = tid + l * 256;
            int row = idx >> 3;
            int kc = (idx & 7) << 2;
            cp_async16(bbase + (uint32_t)(row * ROWSTRIDE + kc) * 4,
                       &et[(size_t)(c0 + row) * D_ + kt * BKF + kc]);
        }
        cp_commit();
    };

    load_stage(0, 0);
    load_stage(1, 1);

    const int NK = D_ / BKF;   // 16
    for (int kt = 0; kt < NK; kt++) {
        if (kt + 1 < NK) cp_wait<1>(); else cp_wait<0>();
        __syncthreads();
        if (kt + 2 < NK) load_stage(kt + 2, (kt + 2) % NSTAGE);

        const int st = kt % NSTAGE;
        const uint32_t* Au = reinterpret_cast<const uint32_t*>(smem + st * STAGE_WORDS);
        const uint32_t* Bu = Au + A_WORDS;

#pragma unroll
        for (int ks = 0; ks < 4; ks++) {
            const int k0 = ks * 8;
            uint32_t a[4][4], b[8][2];
#pragma unroll
            for (int mt = 0; mt < 4; mt++) {
                int r = wm + mt * 16 + g;
                a[mt][0] = Au[r * ROWSTRIDE + k0 + q];
                a[mt][1] = Au[(r + 8) * ROWSTRIDE + k0 + q];
                a[mt][2] = Au[r * ROWSTRIDE + k0 + 4 + q];
                a[mt][3] = Au[(r + 8) * ROWSTRIDE + k0 + 4 + q];
            }
#pragma unroll
            for (int nt = 0; nt < 8; nt++) {
                int rn = wn + nt * 8 + g;
                b[nt][0] = Bu[rn * ROWSTRIDE + k0 + q];
                b[nt][1] = Bu[rn * ROWSTRIDE + k0 + 4 + q];
            }
#pragma unroll
            for (int mt = 0; mt < 4; mt++)
#pragma unroll
                for (int nt = 0; nt < 8; nt++)
                    mma_tf32(acc[mt][nt], a[mt], b[nt], acc[mt][nt]);
        }
    }
    __syncthreads();

    // Epilogue: bias-correct, write dist + per-row max (shared atomicMax)
#pragma unroll
    for (int mt = 0; mt < 4; mt++) {
        float mA = -INFINITY, mB = -INFINITY;
#pragma unroll
        for (int nt = 0; nt < 8; nt++) {
            int row = m0 + wm + mt * 16 + g;
            int col = c0 + wn + nt * 8 + 2 * q;
            float2 v01 = make_float2(acc[mt][nt][0] * BIAS_CORR,
                                     acc[mt][nt][1] * BIAS_CORR);
            float2 v23 = make_float2(acc[mt][nt][2] * BIAS_CORR,
                                     acc[mt][nt][3] * BIAS_CORR);
            *reinterpret_cast<float2*>(&dist[(size_t)row * C_ + col]) = v01;
            *reinterpret_cast<float2*>(&dist[(size_t)(row + 8) * C_ + col]) = v23;
            mA = fmaxf(mA, fmaxf(v01.x, v01.y));
            mB = fmaxf(mB, fmaxf(v23.x, v23.y));
        }
        atomicMax(&smax[wm + mt * 16 + g], fenc(mA));
        atomicMax(&smax[wm + mt * 16 + 8 + g], fenc(mB));
    }
    __syncthreads();
    if (tid < BM)
        g_pmax[(size_t)(m0 + tid) * NNT + ntile] = fdec(smax[tid]);
}

// ---------------------------------------------------------------------------
// Kernel 3: rescue argmax driven by tile maxes + exact recompute of
//           near-max candidates + gather quantize + scatter embed_sum/bins.
// One block per row n, 128 threads.
// ---------------------------------------------------------------------------
#define MARGIN 3e-3f
#define MAXCAND 32

__global__ __launch_bounds__(128)
void rescue_kernel(const float* __restrict__ dist,
                   const float* __restrict__ x,
                   const float* __restrict__ embed,
                   float* __restrict__ quant_out,
                   float* __restrict__ ind_out) {
    const int n = blockIdx.x;
    const int tid = threadIdx.x;
    __shared__ float spm[NNT];
    __shared__ float sred[128];
    __shared__ int scand[MAXCAND];
    __shared__ int scount;
    __shared__ float sM;
    __shared__ float sbest;
    __shared__ int sbidx;

    if (tid < NNT) spm[tid] = g_pmax[(size_t)n * NNT + tid];
    if (tid == 0) { scount = 0; sbest = -INFINITY; sbidx = 0; }
    __syncthreads();
    if (tid == 0) {
        float M = -INFINITY;
#pragma unroll
        for (int t = 0; t < NNT; t++) M = fmaxf(M, spm[t]);
        sM = M;
    }
    __syncthreads();
    const float thresh = sM - MARGIN;

    const float* drow = dist + (size_t)n * C_;
#pragma unroll 1
    for (int t = 0; t < NNT; t++) {
        if (spm[t] >= thresh) {
#pragma unroll
            for (int i = 0; i < 2; i++) {
                int c = t * BN + i * 128 + tid;
                if (drow[c] >= thresh) {
                    int p = atomicAdd(&scount, 1);
                    if (p < MAXCAND) scand[p] = c;
                }
            }
        }
    }
    __syncthreads();
    int ncand = min(scount, MAXCAND);
    if (tid == 0 && ncand > 1) {
        // insertion sort ascending (first-index tie-break like jnp.argmax)
        for (int i = 1; i < ncand; i++) {
            int key = scand[i];
            int j = i - 1;
            while (j >= 0 && scand[j] > key) { scand[j + 1] = scand[j]; j--; }
            scand[j + 1] = key;
        }
    }
    __syncthreads();

    const float4 x4v = reinterpret_cast<const float4*>(x + (size_t)n * D_)[tid];

    for (int ci = 0; ci < ncand; ci++) {
        const int c = scand[ci];
        const float4 e4 = reinterpret_cast<const float4*>(embed + (size_t)c * D_)[tid];
        float p = x4v.x * e4.x + x4v.y * e4.y + x4v.z * e4.z + x4v.w * e4.w;
        sred[tid] = p;
        __syncthreads();
#pragma unroll
        for (int s = 64; s > 0; s >>= 1) {
            if (tid < s) sred[tid] += sred[tid + s];
            __syncthreads();
        }
        if (tid == 0) {
            float v = sred[0];
            if (v > sbest) { sbest = v; sbidx = c; }  // ascending ci keeps lowest idx on tie
        }
        __syncthreads();
    }

    const int ind = sbidx;
    if (tid == 0) {
        ind_out[n] = (float)ind;
        atomicAdd(&g_bins[ind], 1.0f);
    }

    const float4 e4 = reinterpret_cast<const float4*>(embed + (size_t)ind * D_)[tid];
    reinterpret_cast<float4*>(quant_out + (size_t)n * D_)[tid] = e4;
    float* srowp = g_embed_sum + (size_t)ind * D_ + tid * 4;
    atomicAdd(&srowp[0], x4v.x);
    atomicAdd(&srowp[1], x4v.y);
    atomicAdd(&srowp[2], x4v.z);
    atomicAdd(&srowp[3], x4v.w);
}

// ---------------------------------------------------------------------------
// Kernel 4: new_cluster_size + total (parallel; g_total pre-zeroed)
// 4 blocks x 256 threads, 4 elements each.
// ---------------------------------------------------------------------------
__global__ __launch_bounds__(256)
void cluster_size_kernel(const float* __restrict__ cluster_size,
                         float* __restrict__ ncs_out) {
    const int base = blockIdx.x * 1024 + threadIdx.x * 4;
    float4 cs = *reinterpret_cast<const float4*>(&cluster_size[base]);
    float4 bn = *reinterpret_cast<const float4*>(&g_bins[base]);
    float4 v;
    v.x = cs.x * DECAY + bn.x * ONE_MINUS_DECAY;
    v.y = cs.y * DECAY + bn.y * ONE_MINUS_DECAY;
    v.z = cs.z * DECAY + bn.z * ONE_MINUS_DECAY;
    v.w = cs.w * DECAY + bn.w * ONE_MINUS_DECAY;
    *reinterpret_cast<float4*>(&ncs_out[base]) = v;
    float local = v.x + v.y + v.z + v.w;

    __shared__ float red[256];
    red[threadIdx.x] = local;
    __syncthreads();
#pragma unroll
    for (int s = 128; s > 0; s >>= 1) {
        if (threadIdx.x < s) red[threadIdx.x] += red[threadIdx.x + s];
        __syncthreads();
    }
    if (threadIdx.x == 0) atomicAdd(&g_total, red[0]);
}

// ---------------------------------------------------------------------------
// Kernel 5: per-code EMA + normalize. One block per code c, 128 threads,
// float4 vectorized (128 x 4 = 512 elems), shuffle+smem reduction.
// ---------------------------------------------------------------------------
__global__ __launch_bounds__(128)
void embed_update_kernel(const float* __restrict__ embed_avg,
                         const float* __restrict__ ncs,
                         float* __restrict__ nea_out,
                         float* __restrict__ ne_out) {
    const int c = blockIdx.x;
    const int tid = threadIdx.x;

    const float total = g_total;
    const float n_cs = ncs[c];
    const float smoothed = (n_cs + EPS_) / (total + (float)C_ * EPS_) * total;
    const float inv_s = 1.0f / smoothed;

    const float4 ea = reinterpret_cast<const float4*>(embed_avg + (size_t)c * D_)[tid];
    const float4 es = reinterpret_cast<const float4*>(g_embed_sum + (size_t)c * D_)[tid];
    float4 nea;
    nea.x = ea.x * DECAY + es.x * ONE_MINUS_DECAY;
    nea.y = ea.y * DECAY + es.y * ONE_MINUS_DECAY;
    nea.z = ea.z * DECAY + es.z * ONE_MINUS_DECAY;
    nea.w = ea.w * DECAY + es.w * ONE_MINUS_DECAY;
    reinterpret_cast<float4*>(nea_out + (size_t)c * D_)[tid] = nea;

    float4 t;
    t.x = nea.x * inv_s; t.y = nea.y * inv_s;
    t.z = nea.z * inv_s; t.w = nea.w * inv_s;
    float sumsq = t.x * t.x + t.y * t.y + t.z * t.z + t.w * t.w;

    // warp reduce + cross-warp via smem
#pragma unroll
    for (int o = 16; o > 0; o >>= 1)
        sumsq += __shfl_xor_sync(0xFFFFFFFFu, sumsq, o);
    __shared__ float wred[4];
    if ((tid & 31) == 0) wred[tid >> 5] = sumsq;
    __syncthreads();
    float tot = wred[0] + wred[1] + wred[2] + wred[3];

    float norm = fmaxf(sqrtf(tot), 1e-12f);
    float inv_n = 1.0f / norm;
    float4 o4;
    o4.x = t.x * inv_n; o4.y = t.y * inv_n;
    o4.z = t.z * inv_n; o4.w = t.w * inv_n;
    reinterpret_cast<float4*>(ne_out + (size_t)c * D_)[tid] = o4;
}

// ---------------------------------------------------------------------------
// Launch
// ---------------------------------------------------------------------------
extern "C" void kernel_launch(void* const* d_in, const int* in_sizes, int n_in,
                              void* d_out, int out_size) {
    const float* x          = (const float*)d_in[0];  // (16,1024,512)
    const float* embed      = (const float*)d_in[1];  // (1,4096,512)
    const float* cluster_sz = (const float*)d_in[2];  // (1,4096)
    const float* embed_avg  = (const float*)d_in[3];  // (1,4096,512)
    float* out = (float*)d_out;

    float* out_q    = out + OFF_Q;
    float* out_ind  = out + OFF_IND;
    float* out_dist = out + OFF_DIST;
    float* out_ne   = out + OFF_NE;
    float* out_ncs  = out + OFF_NCS;
    float* out_nea  = out + OFF_NEA;

    (void)in_sizes; (void)n_in; (void)out_size;

    zero_kernel<<<ZB, 256>>>();

    static bool attr_done = false;
    if (!attr_done) {
        cudaFuncSetAttribute(dist_mma_kernel,
                             cudaFuncAttributeMaxDynamicSharedMemorySize,
                             SMEM_GEMM_BYTES);
        attr_done = true;
    }
    dim3 ggrid(NNT, NMT);   // (16, 128)
    dist_mma_kernel<<<ggrid, 256, SMEM_GEMM_BYTES>>>(x, embed, out_dist);

    rescue_kernel<<<NTOT, 128>>>(out_dist, x, embed, out_q, out_ind);

    cluster_size_kernel<<<4, 256>>>(cluster_sz, out_ncs);

    embed_update_kernel<<<C_, 128>>>(embed_avg, out_ncs, out_nea, out_ne);
}